// round 10
// baseline (speedup 1.0000x reference)
#include <cuda_runtime.h>
#include <cuda_bf16.h>

// AllReduce(sum over tp=8) + residual add + RMSNorm, fused single pass.
// R10 = R9 (best: 102.6us kernel, DRAM 87.7%, 6951 GB/s) + vectorized
// post-barrier reduce: warp partials are read as 8x float4 (LDS.128
// broadcast, conflict-free) instead of 32 scalar LDS, shortening the serial
// region between the barrier and the out_norm stores.
// Structure (settled by R1-R9 evidence): 1024 thr, 32-reg clamp, 2 CTAs/SM
// (~94% occ), one CTA per token, single accumulator stream of 9 LDG.128,
// streaming ld/st, hidden-store before the single barrier, redundant
// per-thread final reduce, weight loaded post-barrier.

constexpr int TOKENS = 4096;
constexpr int HIDDEN = 4096;
constexpr int TP     = 8;
constexpr int H4     = HIDDEN / 4;        // 1024 float4 per row
constexpr int NTHREADS = 1024;
constexpr int NWARPS  = NTHREADS / 32;    // 32
constexpr float EPS = 1e-6f;

__global__ __launch_bounds__(NTHREADS, 2) void allreduce_rmsnorm_kernel(
    const float4* __restrict__ input,     // [TP, TOKENS, H4]
    const float4* __restrict__ residual,  // [TOKENS, H4]
    const float4* __restrict__ weight,    // [H4]
    float4* __restrict__ out_norm,        // [TOKENS, H4]
    float4* __restrict__ out_hidden)      // [TOKENS, H4]
{
    const int token = blockIdx.x;
    const int tid   = threadIdx.x;        // == element index, H4 = NTHREADS
    const int lane  = tid & 31;
    const int wid   = tid >> 5;

    const size_t row_off   = (size_t)token * H4;
    const size_t tp_stride = (size_t)TOKENS * H4;

    const float4* __restrict__ in_row = input + row_off;

    // Single accumulation stream: 9 independent streaming loads.
    float4 a = __ldcs(&residual[row_off + tid]);

    #pragma unroll
    for (int t = 0; t < TP; t++) {
        float4 v = __ldcs(&in_row[(size_t)t * tp_stride + tid]);
        a.x += v.x; a.y += v.y; a.z += v.z; a.w += v.w;
    }

    float ss = 0.0f;
    ss = fmaf(a.x, a.x, ss); ss = fmaf(a.y, a.y, ss);
    ss = fmaf(a.z, a.z, ss); ss = fmaf(a.w, a.w, ss);

    // Residual-stream output does not depend on rstd: store before the
    // barrier so DRAM stays busy through the reduce window.
    __stcs(&out_hidden[row_off + tid], a);

    // Warp reduce -> smem -> single barrier -> redundant per-thread finish.
    #pragma unroll
    for (int off = 16; off > 0; off >>= 1)
        ss += __shfl_xor_sync(0xFFFFFFFFu, ss, off);

    __shared__ __align__(16) float warp_ss[NWARPS];
    if (lane == 0) warp_ss[wid] = ss;
    __syncthreads();

    // Vectorized broadcast read of the 32 warp partials: 8x LDS.128.
    const float4* warp_ss4 = reinterpret_cast<const float4*>(warp_ss);
    float tot = 0.0f;
    #pragma unroll
    for (int w = 0; w < NWARPS / 4; w++) {
        const float4 p = warp_ss4[w];
        tot += (p.x + p.y) + (p.z + p.w);
    }
    const float rstd = rsqrtf(tot * (1.0f / (float)HIDDEN) + EPS);

    // Normalized output; weight is 16KB, reused by all CTAs -> L2-cached.
    const float4 w = __ldg(&weight[tid]);
    float4 n;
    n.x = a.x * rstd * w.x;
    n.y = a.y * rstd * w.y;
    n.z = a.z * rstd * w.z;
    n.w = a.w * rstd * w.w;
    __stcs(&out_norm[row_off + tid], n);
}

extern "C" void kernel_launch(void* const* d_in, const int* in_sizes, int n_in,
                              void* d_out, int out_size)
{
    const float4* input    = (const float4*)d_in[0];
    const float4* residual = (const float4*)d_in[1];
    const float4* weight   = (const float4*)d_in[2];

    float4* out_norm   = (float4*)d_out;
    float4* out_hidden = (float4*)((float*)d_out + (size_t)TOKENS * HIDDEN);

    allreduce_rmsnorm_kernel<<<TOKENS, NTHREADS>>>(
        input, residual, weight, out_norm, out_hidden);
}

// round 11
// speedup vs baseline: 1.0444x; 1.0444x over previous
#include <cuda_runtime.h>
#include <cuda_bf16.h>

// AllReduce(sum over tp=8) + residual add + RMSNorm, fused single pass.
// FINAL (= R9, best measured: kernel 102.6us, DRAM 87.7%, HBM 6951 GB/s,
// dur_us 106.6). Settled by R1-R10 evidence:
//  - 1024 threads, one CTA per token, 32-reg clamp -> 2 CTAs/SM, ~94% occ.
//  - Single accumulator stream: 9 independent LDG.128 (1 residual + 8 TP)
//    pipelines deepest within the 32-reg budget; any variant with more live
//    accumulator state (dual-stream R6, 2-token R7) or perturbed scheduling
//    (weight hoist R8, float4 smem reduce R10) measured worse.
//  - Streaming ld/st (__ldcs/__stcs): zero-reuse 708MB stream.
//  - Hidden-stream store issued BEFORE the single barrier.
//  - Scalar redundant per-thread final reduce (32 LDS broadcasts) after one
//    __syncthreads; weight __ldg post-barrier (L2-resident, 16KB).
// Traffic is exactly mandatory; kernel sits at the practical HBM ceiling.

constexpr int TOKENS = 4096;
constexpr int HIDDEN = 4096;
constexpr int TP     = 8;
constexpr int H4     = HIDDEN / 4;        // 1024 float4 per row
constexpr int NTHREADS = 1024;
constexpr int NWARPS  = NTHREADS / 32;    // 32
constexpr float EPS = 1e-6f;

__global__ __launch_bounds__(NTHREADS, 2) void allreduce_rmsnorm_kernel(
    const float4* __restrict__ input,     // [TP, TOKENS, H4]
    const float4* __restrict__ residual,  // [TOKENS, H4]
    const float4* __restrict__ weight,    // [H4]
    float4* __restrict__ out_norm,        // [TOKENS, H4]
    float4* __restrict__ out_hidden)      // [TOKENS, H4]
{
    const int token = blockIdx.x;
    const int tid   = threadIdx.x;        // == element index, H4 = NTHREADS
    const int lane  = tid & 31;
    const int wid   = tid >> 5;

    const size_t row_off   = (size_t)token * H4;
    const size_t tp_stride = (size_t)TOKENS * H4;

    const float4* __restrict__ in_row = input + row_off;

    // Single accumulation stream: 9 independent streaming loads.
    float4 a = __ldcs(&residual[row_off + tid]);

    #pragma unroll
    for (int t = 0; t < TP; t++) {
        float4 v = __ldcs(&in_row[(size_t)t * tp_stride + tid]);
        a.x += v.x; a.y += v.y; a.z += v.z; a.w += v.w;
    }

    float ss = 0.0f;
    ss = fmaf(a.x, a.x, ss); ss = fmaf(a.y, a.y, ss);
    ss = fmaf(a.z, a.z, ss); ss = fmaf(a.w, a.w, ss);

    // Residual-stream output does not depend on rstd: store before the
    // barrier so DRAM stays busy through the reduce window.
    __stcs(&out_hidden[row_off + tid], a);

    // Warp reduce -> smem -> single barrier -> redundant per-thread finish.
    #pragma unroll
    for (int off = 16; off > 0; off >>= 1)
        ss += __shfl_xor_sync(0xFFFFFFFFu, ss, off);

    __shared__ float warp_ss[NWARPS];
    if (lane == 0) warp_ss[wid] = ss;
    __syncthreads();

    float tot = 0.0f;
    #pragma unroll
    for (int w = 0; w < NWARPS; w++)
        tot += warp_ss[w];
    const float rstd = rsqrtf(tot * (1.0f / (float)HIDDEN) + EPS);

    // Normalized output; weight is 16KB, reused by all CTAs -> L2-cached.
    const float4 w = __ldg(&weight[tid]);
    float4 n;
    n.x = a.x * rstd * w.x;
    n.y = a.y * rstd * w.y;
    n.z = a.z * rstd * w.z;
    n.w = a.w * rstd * w.w;
    __stcs(&out_norm[row_off + tid], n);
}

extern "C" void kernel_launch(void* const* d_in, const int* in_sizes, int n_in,
                              void* d_out, int out_size)
{
    const float4* input    = (const float4*)d_in[0];
    const float4* residual = (const float4*)d_in[1];
    const float4* weight   = (const float4*)d_in[2];

    float4* out_norm   = (float4*)d_out;
    float4* out_hidden = (float4*)((float*)d_out + (size_t)TOKENS * HIDDEN);

    allreduce_rmsnorm_kernel<<<TOKENS, NTHREADS>>>(
        input, residual, weight, out_norm, out_hidden);
}